// round 1
// baseline (speedup 1.0000x reference)
#include <cuda_runtime.h>
#include <math.h>

#define NB 8192
#define NS 64
#define NH 2048
#define ND 1024
#define NE 8
#define NGROUP 16   // (expert, sel) pairs

// Scratch (permuted row order). __device__ globals per harness rules.
__device__ float g_h1[NB * NH];    // 64 MB
__device__ float g_mid[NB * ND];   // 32 MB
__device__ float g_h2[NB * NH];    // 64 MB
__device__ int   g_perm[NB];
__device__ int   g_goff[NGROUP + 1];
__device__ int   g_pos[NGROUP];

// ---------------------------------------------------------------------------
// Counting sort of rows by key = expert*2 + sel. Final output is independent
// of within-group ordering (each row's math is self-contained), so atomic
// placement order does not affect the result.
// ---------------------------------------------------------------------------
__global__ void sort_kernel(const int* __restrict__ ei, const int* __restrict__ hp) {
    __shared__ int cnt[NGROUP];
    int t = threadIdx.x;
    if (t < NGROUP) cnt[t] = 0;
    __syncthreads();
    for (int i = t; i < NB; i += blockDim.x)
        atomicAdd(&cnt[ei[i] * 2 + (hp[i] != 0)], 1);
    __syncthreads();
    if (t == 0) {
        int acc = 0;
        for (int k = 0; k < NGROUP; k++) { g_goff[k] = acc; g_pos[k] = acc; acc += cnt[k]; }
        g_goff[NGROUP] = acc;
    }
    __syncthreads();
    for (int i = t; i < NB; i += blockDim.x) {
        int key = ei[i] * 2 + (hp[i] != 0);
        g_perm[atomicAdd(&g_pos[key], 1)] = i;
    }
}

__device__ __forceinline__ float gelu_exact(float x) {
    return 0.5f * x * (1.0f + erff(x * 0.70710678118654752f));
}

// ---------------------------------------------------------------------------
// Grouped GEMM: C[m, n0:n0+128] = act(A[m,:] @ W + bias) for rows m in one
// (expert, sel) group. 128x128x16 tile, 256 threads, 8x8 microtile (split as
// 4+4 halves at stride 64 for conflict-free float4 SMEM access).
// asel/csel: 0 = external ptr, 1 = g_h1, 2 = g_mid, 3 = g_h2.
// ---------------------------------------------------------------------------
template <int ACT>
__global__ __launch_bounds__(256, 2)
void gemm_grouped(const float* __restrict__ Aext, int asel,
                  const float* __restrict__ W1e, const float* __restrict__ W2e,
                  const float* __restrict__ b1e, const float* __restrict__ b2e,
                  float* __restrict__ Cext, int csel,
                  int K, int N, int in_perm, int out_perm)
{
    int g = blockIdx.y;
    int start = g_goff[g], end = g_goff[g + 1];
    int m0 = start + blockIdx.x * 128;
    if (m0 >= end) return;

    int e = g >> 1, sel = g & 1;
    const float* A = (asel == 0) ? Aext : (asel == 1 ? g_h1 : (asel == 2 ? g_mid : g_h2));
    float*       C = (csel == 0) ? Cext : (csel == 1 ? g_h1 : (csel == 2 ? g_mid : g_h2));
    const float* W    = (sel ? W2e : W1e) + (size_t)e * K * N;
    const float* bias = (sel ? b2e : b1e) + (size_t)e * N;
    int n0 = blockIdx.z * 128;

    __shared__ float As[16][132];
    __shared__ float Ws[16][132];

    int tid = threadIdx.x;
    int tx = tid & 15, ty = tid >> 4;

    // A-load mapping: each thread loads 8 contiguous K-values for one row
    int am = tid >> 1;            // 0..127
    int ak = (tid & 1) * 8;       // 0 or 8
    const float* Arow = nullptr;
    {
        int arow = m0 + am;
        if (arow < end) {
            int r = in_perm ? g_perm[arow] : arow;
            Arow = A + (size_t)r * K;
        }
    }
    // W-load mapping: 16 k-rows x 128 n-cols, 8 floats per thread
    int wk = tid >> 4, wn = (tid & 15) * 8;

    float acc[8][8];
#pragma unroll
    for (int i = 0; i < 8; i++)
#pragma unroll
        for (int j = 0; j < 8; j++) acc[i][j] = 0.0f;

    for (int k0 = 0; k0 < K; k0 += 16) {
        float4 a0, a1;
        if (Arow) {
            a0 = *(const float4*)(Arow + k0 + ak);
            a1 = *(const float4*)(Arow + k0 + ak + 4);
        } else {
            a0 = make_float4(0.f, 0.f, 0.f, 0.f); a1 = a0;
        }
        As[ak + 0][am] = a0.x; As[ak + 1][am] = a0.y;
        As[ak + 2][am] = a0.z; As[ak + 3][am] = a0.w;
        As[ak + 4][am] = a1.x; As[ak + 5][am] = a1.y;
        As[ak + 6][am] = a1.z; As[ak + 7][am] = a1.w;

        const float* Wp = W + (size_t)(k0 + wk) * N + n0 + wn;
        float4 w0 = *(const float4*)(Wp);
        float4 w1 = *(const float4*)(Wp + 4);
        *(float4*)&Ws[wk][wn]     = w0;
        *(float4*)&Ws[wk][wn + 4] = w1;

        __syncthreads();

#pragma unroll
        for (int k = 0; k < 16; k++) {
            float a[8], b[8];
            float4 av0 = *(const float4*)&As[k][ty * 4];
            float4 av1 = *(const float4*)&As[k][64 + ty * 4];
            a[0] = av0.x; a[1] = av0.y; a[2] = av0.z; a[3] = av0.w;
            a[4] = av1.x; a[5] = av1.y; a[6] = av1.z; a[7] = av1.w;
            float4 bv0 = *(const float4*)&Ws[k][tx * 4];
            float4 bv1 = *(const float4*)&Ws[k][64 + tx * 4];
            b[0] = bv0.x; b[1] = bv0.y; b[2] = bv0.z; b[3] = bv0.w;
            b[4] = bv1.x; b[5] = bv1.y; b[6] = bv1.z; b[7] = bv1.w;
#pragma unroll
            for (int i = 0; i < 8; i++)
#pragma unroll
                for (int j = 0; j < 8; j++)
                    acc[i][j] += a[i] * b[j];
        }
        __syncthreads();
    }

    // Epilogue: bias + activation + store (half-split column layout)
    float bv[8];
#pragma unroll
    for (int j = 0; j < 8; j++) {
        int col = (j < 4) ? (tx * 4 + j) : (64 + tx * 4 + (j - 4));
        bv[j] = bias[n0 + col];
    }
#pragma unroll
    for (int i = 0; i < 8; i++) {
        int mrow = m0 + ((i < 4) ? (ty * 4 + i) : (64 + ty * 4 + (i - 4)));
        if (mrow >= end) continue;
        int orow = out_perm ? g_perm[mrow] : mrow;
        float* Crow = C + (size_t)orow * N + n0;
        float v[8];
#pragma unroll
        for (int j = 0; j < 8; j++) {
            float x = acc[i][j] + bv[j];
            v[j] = ACT ? gelu_exact(x) : x;
        }
        *(float4*)(Crow + tx * 4)      = make_float4(v[0], v[1], v[2], v[3]);
        *(float4*)(Crow + 64 + tx * 4) = make_float4(v[4], v[5], v[6], v[7]);
    }
}

// ---------------------------------------------------------------------------
// Row-wise LayerNorm over g_mid (permuted rows), in place. D = 1024.
// ---------------------------------------------------------------------------
__global__ void ln_kernel(const int* __restrict__ ei,
                          const float* __restrict__ ln_g,
                          const float* __restrict__ ln_b)
{
    int r = blockIdx.x;
    int orig = g_perm[r];
    int e = ei[orig];
    float* row = g_mid + (size_t)r * ND;
    int t = threadIdx.x;

    float v[4];
    float s = 0.0f;
#pragma unroll
    for (int i = 0; i < 4; i++) { v[i] = row[t + i * 256]; s += v[i]; }

    __shared__ float red[256];
    red[t] = s; __syncthreads();
    for (int o = 128; o > 0; o >>= 1) { if (t < o) red[t] += red[t + o]; __syncthreads(); }
    float mu = red[0] * (1.0f / ND);
    __syncthreads();

    float q = 0.0f;
#pragma unroll
    for (int i = 0; i < 4; i++) { float d = v[i] - mu; q += d * d; }
    red[t] = q; __syncthreads();
    for (int o = 128; o > 0; o >>= 1) { if (t < o) red[t] += red[t + o]; __syncthreads(); }
    float var = red[0] * (1.0f / ND);
    float inv = rsqrtf(var + 1e-5f);

#pragma unroll
    for (int i = 0; i < 4; i++) {
        int c = t + i * 256;
        row[c] = (v[i] - mu) * inv * ln_g[(size_t)e * ND + c] + ln_b[(size_t)e * ND + c];
    }
}

// ---------------------------------------------------------------------------
extern "C" void kernel_launch(void* const* d_in, const int* in_sizes, int n_in,
                              void* d_out, int out_size)
{
    const float* raw = (const float*)d_in[0];
    const int*   hp  = (const int*)d_in[1];
    const int*   ei  = (const int*)d_in[2];
    const float* pw1 = (const float*)d_in[3],  *pb1 = (const float*)d_in[4];
    const float* pw2 = (const float*)d_in[5],  *pb2 = (const float*)d_in[6];
    const float* qw1 = (const float*)d_in[7],  *qb1 = (const float*)d_in[8];
    const float* qw2 = (const float*)d_in[9],  *qb2 = (const float*)d_in[10];
    const float* lg  = (const float*)d_in[11], *lb  = (const float*)d_in[12];
    const float* tw1 = (const float*)d_in[13], *tb1 = (const float*)d_in[14];
    const float* tw2 = (const float*)d_in[15], *tb2 = (const float*)d_in[16];
    float* out = (float*)d_out;

    sort_kernel<<<1, 256>>>(ei, hp);

    // Stage 1: h1 = gelu(x @ w1 + b1), w1 = pw1|qw1 per sel. [B,64] -> [B,2048]
    gemm_grouped<1><<<dim3(64, NGROUP, NH / 128), 256>>>(
        raw, 0, pw1, qw1, pb1, qb1, nullptr, 1, NS, NH, /*in_perm=*/1, /*out_perm=*/0);

    // Stage 2: mixed = h1 @ w2 + b2. [B,2048] -> [B,1024]
    gemm_grouped<0><<<dim3(64, NGROUP, ND / 128), 256>>>(
        nullptr, 1, pw2, qw2, pb2, qb2, nullptr, 2, NH, ND, 0, 0);

    // LayerNorm (in place on g_mid)
    ln_kernel<<<NB, 256>>>(ei, lg, lb);

    // Stage 3: h2 = gelu(normed @ tw1 + tb1). [B,1024] -> [B,2048]
    gemm_grouped<1><<<dim3(64, NGROUP, NH / 128), 256>>>(
        nullptr, 2, tw1, tw1, tb1, tb1, nullptr, 3, ND, NH, 0, 0);

    // Stage 4: out = h2 @ tw2 + tb2, scattered to original rows. [B,2048] -> [B,1024]
    gemm_grouped<0><<<dim3(64, NGROUP, ND / 128), 256>>>(
        nullptr, 3, tw2, tw2, tb2, tb2, out, 0, NH, ND, 0, /*out_perm=*/1);
}

// round 10
// speedup vs baseline: 2.6506x; 2.6506x over previous
#include <cuda_runtime.h>
#include <math.h>
#include <stdint.h>

#define NB 8192
#define NS 64
#define NH 2048
#define ND 1024
#define NE 8
#define NGROUP 16
#define BM 128
#define BN 128
#define BK 32
#define STAGES 3
#define APITCH 36                        // floats; 144B, 16B-aligned, conflict-free
#define TILE_F (128 * APITCH)            // floats per SMEM tile
#define SMEM_BYTES (STAGES * 2 * TILE_F * 4)   // 110,592 B
#define MAXTILES 80

// ---------------- device scratch (allowed: __device__ globals) --------------
__device__ float g_x  [(NB + BM) * NS];        // rounded + permuted raw_state
__device__ float g_h1 [(NB + BM) * NH];
__device__ float g_mid[(NB + BM) * ND];
__device__ float g_h2 [(NB + BM) * NH];
__device__ float g_wt1[NGROUP * NH * NS];      // [16][2048][64]   (tf32-rounded, [N][K])
__device__ float g_wt2[NGROUP * ND * NH];      // [16][1024][2048]
__device__ float g_wt3[NE * NH * ND];          // [8][2048][1024]
__device__ float g_wt4[NE * ND * NH];          // [8][1024][2048]
__device__ int   g_perm[NB];
__device__ int   g_goff[NGROUP + 1];
__device__ int   g_pos[NGROUP];
__device__ int   g_tile_g[MAXTILES];
__device__ int   g_tile_m0[MAXTILES];
__device__ int   g_ntiles;

// ---------------- helpers ---------------------------------------------------
__device__ __forceinline__ uint32_t smem_u32(const void* p) {
    uint32_t a;
    asm("{ .reg .u64 t; cvta.to.shared.u64 t, %1; cvt.u32.u64 %0, t; }" : "=r"(a) : "l"(p));
    return a;
}
__device__ __forceinline__ void cp16(uint32_t d, const void* s) {
    asm volatile("cp.async.cg.shared.global [%0], [%1], 16;" :: "r"(d), "l"(s));
}
__device__ __forceinline__ void cp_commit() { asm volatile("cp.async.commit_group;" ::: "memory"); }
template <int N_> __device__ __forceinline__ void cp_wait() {
    asm volatile("cp.async.wait_group %0;" :: "n"(N_) : "memory");
}
__device__ __forceinline__ float to_tf32(float x) {
    uint32_t u;
    asm("cvt.rna.tf32.f32 %0, %1;" : "=r"(u) : "f"(x));
    return __uint_as_float(u);
}
__device__ __forceinline__ void mma_tf32(float* d, uint32_t a0, uint32_t a1, uint32_t a2,
                                         uint32_t a3, uint32_t b0, uint32_t b1) {
    asm volatile(
        "mma.sync.aligned.m16n8k8.row.col.f32.tf32.tf32.f32 "
        "{%0,%1,%2,%3}, {%4,%5,%6,%7}, {%8,%9}, {%0,%1,%2,%3};"
        : "+f"(d[0]), "+f"(d[1]), "+f"(d[2]), "+f"(d[3])
        : "r"(a0), "r"(a1), "r"(a2), "r"(a3), "r"(b0), "r"(b1));
}
__device__ __forceinline__ float gelu_exact(float x) {
    return 0.5f * x * (1.0f + erff(x * 0.70710678118654752f));
}

// ---------------------------------------------------------------------------
// Sort rows by (expert, sel); build group offsets + tile list.
// ---------------------------------------------------------------------------
__global__ void sort_kernel(const int* __restrict__ ei, const int* __restrict__ hp) {
    __shared__ int cnt[NGROUP];
    int t = threadIdx.x;
    if (t < NGROUP) cnt[t] = 0;
    __syncthreads();
    for (int i = t; i < NB; i += blockDim.x)
        atomicAdd(&cnt[ei[i] * 2 + (hp[i] != 0)], 1);
    __syncthreads();
    if (t == 0) {
        int acc = 0;
        for (int k = 0; k < NGROUP; k++) { g_goff[k] = acc; g_pos[k] = acc; acc += cnt[k]; }
        g_goff[NGROUP] = acc;
        int nt = 0;
        for (int g = 0; g < NGROUP; g++)
            for (int m0 = g_goff[g]; m0 < g_goff[g + 1]; m0 += BM) {
                g_tile_g[nt] = g; g_tile_m0[nt] = m0; nt++;
            }
        g_ntiles = nt;   // <= 16 + 64 = 80
    }
    __syncthreads();
    for (int i = t; i < NB; i += blockDim.x) {
        int key = ei[i] * 2 + (hp[i] != 0);
        g_perm[atomicAdd(&g_pos[key], 1)] = i;
    }
}

// ---------------------------------------------------------------------------
// g_x[i][:] = tf32_round(raw[g_perm[i]][:])  (permute + round once)
// ---------------------------------------------------------------------------
__global__ void prep_x(const float* __restrict__ raw) {
    int idx = blockIdx.x * blockDim.x + threadIdx.x;
    if (idx >= NB * NS) return;
    int i = idx / NS, c = idx % NS;
    g_x[idx] = to_tf32(raw[(size_t)g_perm[i] * NS + c]);
}

// ---------------------------------------------------------------------------
// Transpose W[mat][K][N] -> WT[mat][N][K], rounding to tf32.
// ---------------------------------------------------------------------------
__global__ void transpose_k(const float* __restrict__ src, int dsel, int K, int N,
                            long srcStride, long dstStride, long dstOff)
{
    float* dst = (dsel == 1) ? g_wt1 : (dsel == 2) ? g_wt2 : (dsel == 3) ? g_wt3 : g_wt4;
    int mat = blockIdx.z;
    src += (size_t)mat * srcStride;
    dst += (size_t)mat * dstStride + dstOff;
    __shared__ float t[32][33];
    int x = blockIdx.x * 32 + threadIdx.x;  // N index
    int y0 = blockIdx.y * 32;               // K base
#pragma unroll
    for (int i = threadIdx.y; i < 32; i += 8)
        t[i][threadIdx.x] = src[(size_t)(y0 + i) * N + x];
    __syncthreads();
    int xo = blockIdx.x * 32;
#pragma unroll
    for (int i = threadIdx.y; i < 32; i += 8)
        dst[(size_t)(xo + i) * K + y0 + threadIdx.x] = to_tf32(t[threadIdx.x][i]);
}

// ---------------------------------------------------------------------------
// Grouped GEMM via mma.sync tf32 (HMMA — legal on plain sm_103 target).
// C[tile rows, n0:n0+128] = act(A @ WT^T + bias).
// A: [rows][K] fp32 (tf32-rounded). WT: [N][K] fp32 (tf32-rounded).
// 8 warps = 2(M) x 4(N); warp tile 64x32; 4x4 m16n8k8 MMAs per warp.
// ---------------------------------------------------------------------------
template <int ACT, int OUT_PERM, int RND>
__global__ void __launch_bounds__(256, 2)
gemm_mma(int asel, int bsel, int csel,
         float* __restrict__ Cext,
         const float* __restrict__ bp, const float* __restrict__ bq,
         int K, int N, int wslot_g)
{
    int bx = blockIdx.x;
    if (bx >= g_ntiles) return;
    int g   = g_tile_g[bx];
    int m0  = g_tile_m0[bx];
    int end = g_goff[g + 1];
    int n0  = (int)blockIdx.y * BN;

    const float* A = (asel == 0) ? g_x : (asel == 1) ? g_h1 : (asel == 2) ? g_mid : g_h2;
    float* C = (csel == 0) ? Cext : (csel == 1) ? g_h1 : (csel == 2) ? g_mid : g_h2;
    int slot = wslot_g ? g : (g >> 1);
    const float* BT = ((bsel == 1) ? g_wt1 : (bsel == 2) ? g_wt2 : (bsel == 3) ? g_wt3 : g_wt4)
                      + (size_t)slot * (size_t)N * (size_t)K;
    const float* bias = ((g & 1) ? bq : bp) + (size_t)(g >> 1) * N + n0;

    const float* Ag = A + (size_t)m0 * K;     // tile rows contiguous (scratch padded)
    const float* Bg = BT + (size_t)n0 * K;

    extern __shared__ float smem[];
    float* Asm = smem;                        // [STAGES][TILE_F]
    float* Bsm = smem + STAGES * TILE_F;
    uint32_t sa = smem_u32(Asm), sb = smem_u32(Bsm);

    int tid = threadIdx.x, wid = tid >> 5, lid = tid & 31;
    int gi = lid >> 2, t = lid & 3;           // groupID, threadID_in_group
    int mw = (wid & 1) * 64;                  // warp M offset
    int nw = (wid >> 1) * 32;                 // warp N offset

    float acc[4][4][4];
#pragma unroll
    for (int i = 0; i < 4; i++)
#pragma unroll
        for (int j = 0; j < 4; j++)
#pragma unroll
            for (int k = 0; k < 4; k++) acc[i][j][k] = 0.0f;

    int nchunks = K / BK;

    auto load_chunk = [&](int c, int s) {
        int k0 = c * BK;
        uint32_t as = sa + s * TILE_F * 4, bs = sb + s * TILE_F * 4;
#pragma unroll
        for (int i = 0; i < 4; i++) {
            int f = tid + (i << 8);           // float4 id 0..1023
            int row = f >> 3, c4 = (f & 7) << 2;
            uint32_t so = (uint32_t)(row * APITCH + c4) * 4;
            cp16(as + so, Ag + (size_t)row * K + k0 + c4);
            cp16(bs + so, Bg + (size_t)row * K + k0 + c4);
        }
        cp_commit();
    };

    int pl = nchunks < STAGES ? nchunks : STAGES;
    for (int c = 0; c < pl; c++) load_chunk(c, c);

    for (int c = 0; c < nchunks; c++) {
        int s = c % STAGES;
        if (c + STAGES <= nchunks) { cp_wait<STAGES - 1>(); } else { cp_wait<0>(); }
        __syncthreads();

        const float* As = Asm + s * TILE_F;
        const float* Bs = Bsm + s * TILE_F;
#pragma unroll
        for (int k8 = 0; k8 < 4; k8++) {
            int kk = k8 * 8;
            uint32_t bf[4][2];
#pragma unroll
            for (int nt = 0; nt < 4; nt++) {
                const float* bpx = Bs + (nw + nt * 8 + gi) * APITCH + kk + t;
                bf[nt][0] = __float_as_uint(bpx[0]);
                bf[nt][1] = __float_as_uint(bpx[4]);
            }
#pragma unroll
            for (int mt = 0; mt < 4; mt++) {
                const float* ap0 = As + (mw + mt * 16 + gi) * APITCH + kk + t;
                const float* ap1 = ap0 + 8 * APITCH;
                uint32_t a0 = __float_as_uint(ap0[0]);
                uint32_t a1 = __float_as_uint(ap1[0]);
                uint32_t a2 = __float_as_uint(ap0[4]);
                uint32_t a3 = __float_as_uint(ap1[4]);
#pragma unroll
                for (int nt = 0; nt < 4; nt++)
                    mma_tf32(acc[mt][nt], a0, a1, a2, a3, bf[nt][0], bf[nt][1]);
            }
        }
        __syncthreads();
        int cn = c + STAGES;
        if (cn < nchunks) load_chunk(cn, s);
    }

    // Epilogue: bias + activation (+ tf32 round) + store
#pragma unroll
    for (int mt = 0; mt < 4; mt++) {
        int r0 = m0 + mw + mt * 16 + gi;
        int r1 = r0 + 8;
        bool v0 = r0 < end, v1 = r1 < end;
        int o0 = v0 ? (OUT_PERM ? g_perm[r0] : r0) : 0;
        int o1 = v1 ? (OUT_PERM ? g_perm[r1] : r1) : 0;
        float* C0 = C + (size_t)o0 * N + n0;
        float* C1 = C + (size_t)o1 * N + n0;
#pragma unroll
        for (int nt = 0; nt < 4; nt++) {
            int lc = nw + nt * 8 + 2 * t;
            float b0v = bias[lc], b1v = bias[lc + 1];
            float x0 = acc[mt][nt][0] + b0v, x1 = acc[mt][nt][1] + b1v;
            float x2 = acc[mt][nt][2] + b0v, x3 = acc[mt][nt][3] + b1v;
            if (ACT) {
                x0 = gelu_exact(x0); x1 = gelu_exact(x1);
                x2 = gelu_exact(x2); x3 = gelu_exact(x3);
            }
            if (RND) {
                x0 = to_tf32(x0); x1 = to_tf32(x1);
                x2 = to_tf32(x2); x3 = to_tf32(x3);
            }
            if (v0) *(float2*)(C0 + lc) = make_float2(x0, x1);
            if (v1) *(float2*)(C1 + lc) = make_float2(x2, x3);
        }
    }
}

// ---------------------------------------------------------------------------
// Row-wise LayerNorm over g_mid (permuted rows), in place; output tf32-rounded.
// ---------------------------------------------------------------------------
__global__ void ln_kernel(const int* __restrict__ ei,
                          const float* __restrict__ ln_g,
                          const float* __restrict__ ln_b)
{
    int r = blockIdx.x;
    int orig = g_perm[r];
    int e = ei[orig];
    float* row = g_mid + (size_t)r * ND;
    int t = threadIdx.x;

    float v[4];
    float s = 0.0f;
#pragma unroll
    for (int i = 0; i < 4; i++) { v[i] = row[t + i * 256]; s += v[i]; }

    __shared__ float red[256];
    red[t] = s; __syncthreads();
    for (int o = 128; o > 0; o >>= 1) { if (t < o) red[t] += red[t + o]; __syncthreads(); }
    float mu = red[0] * (1.0f / ND);
    __syncthreads();

    float q = 0.0f;
#pragma unroll
    for (int i = 0; i < 4; i++) { float d = v[i] - mu; q += d * d; }
    red[t] = q; __syncthreads();
    for (int o = 128; o > 0; o >>= 1) { if (t < o) red[t] += red[t + o]; __syncthreads(); }
    float var = red[0] * (1.0f / ND);
    float inv = rsqrtf(var + 1e-5f);

#pragma unroll
    for (int i = 0; i < 4; i++) {
        int c = t + i * 256;
        row[c] = to_tf32((v[i] - mu) * inv * ln_g[(size_t)e * ND + c] + ln_b[(size_t)e * ND + c]);
    }
}

// ---------------------------------------------------------------------------
extern "C" void kernel_launch(void* const* d_in, const int* in_sizes, int n_in,
                              void* d_out, int out_size)
{
    const float* raw = (const float*)d_in[0];
    const int*   hp  = (const int*)d_in[1];
    const int*   ei  = (const int*)d_in[2];
    const float* pw1 = (const float*)d_in[3],  *pb1 = (const float*)d_in[4];
    const float* pw2 = (const float*)d_in[5],  *pb2 = (const float*)d_in[6];
    const float* qw1 = (const float*)d_in[7],  *qb1 = (const float*)d_in[8];
    const float* qw2 = (const float*)d_in[9],  *qb2 = (const float*)d_in[10];
    const float* lg  = (const float*)d_in[11], *lb  = (const float*)d_in[12];
    const float* tw1 = (const float*)d_in[13], *tb1 = (const float*)d_in[14];
    const float* tw2 = (const float*)d_in[15], *tb2 = (const float*)d_in[16];
    float* out = (float*)d_out;

    cudaFuncSetAttribute(gemm_mma<1, 0, 1>, cudaFuncAttributeMaxDynamicSharedMemorySize, SMEM_BYTES);
    cudaFuncSetAttribute(gemm_mma<0, 0, 1>, cudaFuncAttributeMaxDynamicSharedMemorySize, SMEM_BYTES);
    cudaFuncSetAttribute(gemm_mma<0, 1, 0>, cudaFuncAttributeMaxDynamicSharedMemorySize, SMEM_BYTES);

    sort_kernel<<<1, 256>>>(ei, hp);
    prep_x<<<(NB * NS + 255) / 256, 256>>>(raw);

    // Weight transposes (+ tf32 rounding): W[K][N] -> WT[N][K]
    dim3 tb(32, 8);
    transpose_k<<<dim3(NH / 32, NS / 32, NE), tb>>>(pw1, 1, NS, NH, (long)NS * NH, 2L * NH * NS, 0);
    transpose_k<<<dim3(NH / 32, NS / 32, NE), tb>>>(qw1, 1, NS, NH, (long)NS * NH, 2L * NH * NS, (long)NH * NS);
    transpose_k<<<dim3(ND / 32, NH / 32, NE), tb>>>(pw2, 2, NH, ND, (long)NH * ND, 2L * ND * NH, 0);
    transpose_k<<<dim3(ND / 32, NH / 32, NE), tb>>>(qw2, 2, NH, ND, (long)NH * ND, 2L * ND * NH, (long)ND * NH);
    transpose_k<<<dim3(NH / 32, ND / 32, NE), tb>>>(tw1, 3, ND, NH, (long)ND * NH, (long)NH * ND, 0);
    transpose_k<<<dim3(ND / 32, NH / 32, NE), tb>>>(tw2, 4, NH, ND, (long)NH * ND, (long)ND * NH, 0);

    // Stage 1: h1 = gelu(x @ w1 + b1)   [B,64] -> [B,2048]
    gemm_mma<1, 0, 1><<<dim3(MAXTILES, NH / BN), 256, SMEM_BYTES>>>(
        0, 1, 1, nullptr, pb1, qb1, NS, NH, 1);
    // Stage 2: mixed = h1 @ w2 + b2     [B,2048] -> [B,1024]
    gemm_mma<0, 0, 1><<<dim3(MAXTILES, ND / BN), 256, SMEM_BYTES>>>(
        1, 2, 2, nullptr, pb2, qb2, NH, ND, 1);
    // LayerNorm (in place on g_mid, tf32-rounded)
    ln_kernel<<<NB, 256>>>(ei, lg, lb);
    // Stage 3: h2 = gelu(normed @ tw1 + tb1)  [B,1024] -> [B,2048]
    gemm_mma<1, 0, 1><<<dim3(MAXTILES, NH / BN), 256, SMEM_BYTES>>>(
        2, 3, 3, nullptr, tb1, tb1, ND, NH, 0);
    // Stage 4: out = h2 @ tw2 + tb2, scatter to original rows
    gemm_mma<0, 1, 0><<<dim3(MAXTILES, ND / BN), 256, SMEM_BYTES>>>(
        3, 4, 0, out, tb2, tb2, NH, ND, 0);
}

// round 12
// speedup vs baseline: 4.2656x; 1.6093x over previous
#include <cuda_runtime.h>
#include <cuda_fp16.h>
#include <math.h>
#include <stdint.h>

#define NB 8192
#define NS 64
#define NH 2048
#define ND 1024
#define NE 8
#define NGROUP 16
#define BM 128
#define BN 128
#define BK 32
#define STAGES 4
#define HPITCH 40                          // halves; 80B = 5x16B (odd) -> conflict-free ldmatrix
#define TILE_H (128 * HPITCH)              // halves per SMEM tile
#define STAGE_BYTES (TILE_H * 2)           // 10240 B
#define SMEM_BYTES (STAGES * 2 * STAGE_BYTES)   // 81920 B
#define MAXTILES 80

// ---------------- device scratch (allowed: __device__ globals) --------------
__device__ __align__(128) __half g_x  [(NB + BM) * NS];
__device__ __align__(128) __half g_h1 [(NB + BM) * NH];
__device__ __align__(128) __half g_mid[(NB + BM) * ND];
__device__ __align__(128) __half g_h2 [(NB + BM) * NH];
__device__ __align__(128) __half g_wt1[NGROUP * NH * NS];   // [16][2048][64]  ([N][K])
__device__ __align__(128) __half g_wt2[NGROUP * ND * NH];
__device__ __align__(128) __half g_wt3[NE * NH * ND];
__device__ __align__(128) __half g_wt4[NE * ND * NH];
__device__ int g_perm[NB];
__device__ int g_goff[NGROUP + 1];
__device__ int g_pos[NGROUP];
__device__ int g_tile_g[MAXTILES];
__device__ int g_tile_m0[MAXTILES];
__device__ int g_ntiles;

// ---------------- helpers ---------------------------------------------------
__device__ __forceinline__ uint32_t smem_u32(const void* p) {
    uint32_t a;
    asm("{ .reg .u64 t; cvta.to.shared.u64 t, %1; cvt.u32.u64 %0, t; }" : "=r"(a) : "l"(p));
    return a;
}
__device__ __forceinline__ void cp16(uint32_t d, const void* s) {
    asm volatile("cp.async.cg.shared.global [%0], [%1], 16;" :: "r"(d), "l"(s));
}
__device__ __forceinline__ void cp_commit() { asm volatile("cp.async.commit_group;" ::: "memory"); }
template <int N_> __device__ __forceinline__ void cp_wait() {
    asm volatile("cp.async.wait_group %0;" :: "n"(N_) : "memory");
}
__device__ __forceinline__ void ldsm4(uint32_t& r0, uint32_t& r1, uint32_t& r2, uint32_t& r3,
                                      uint32_t addr) {
    asm volatile("ldmatrix.sync.aligned.m8n8.x4.shared.b16 {%0,%1,%2,%3}, [%4];"
                 : "=r"(r0), "=r"(r1), "=r"(r2), "=r"(r3) : "r"(addr));
}
__device__ __forceinline__ void mma_f16(float* d, uint32_t a0, uint32_t a1, uint32_t a2,
                                        uint32_t a3, uint32_t b0, uint32_t b1) {
    asm volatile(
        "mma.sync.aligned.m16n8k16.row.col.f32.f16.f16.f32 "
        "{%0,%1,%2,%3}, {%4,%5,%6,%7}, {%8,%9}, {%0,%1,%2,%3};"
        : "+f"(d[0]), "+f"(d[1]), "+f"(d[2]), "+f"(d[3])
        : "r"(a0), "r"(a1), "r"(a2), "r"(a3), "r"(b0), "r"(b1));
}
__device__ __forceinline__ float gelu_exact(float x) {
    return 0.5f * x * (1.0f + erff(x * 0.70710678118654752f));
}

// ---------------------------------------------------------------------------
// Sort rows by (expert, sel); build group offsets + tile list.
// ---------------------------------------------------------------------------
__global__ void sort_kernel(const int* __restrict__ ei, const int* __restrict__ hp) {
    __shared__ int cnt[NGROUP];
    int t = threadIdx.x;
    if (t < NGROUP) cnt[t] = 0;
    __syncthreads();
    for (int i = t; i < NB; i += blockDim.x)
        atomicAdd(&cnt[ei[i] * 2 + (hp[i] != 0)], 1);
    __syncthreads();
    if (t == 0) {
        int acc = 0;
        for (int k = 0; k < NGROUP; k++) { g_goff[k] = acc; g_pos[k] = acc; acc += cnt[k]; }
        g_goff[NGROUP] = acc;
        int nt = 0;
        for (int g = 0; g < NGROUP; g++)
            for (int m0 = g_goff[g]; m0 < g_goff[g + 1]; m0 += BM) {
                g_tile_g[nt] = g; g_tile_m0[nt] = m0; nt++;
            }
        g_ntiles = nt;   // <= 16 + 64 = 80
    }
    __syncthreads();
    for (int i = t; i < NB; i += blockDim.x) {
        int key = ei[i] * 2 + (hp[i] != 0);
        g_perm[atomicAdd(&g_pos[key], 1)] = i;
    }
}

// ---------------------------------------------------------------------------
// g_x[i][:] = fp16(raw[g_perm[i]][:])
// ---------------------------------------------------------------------------
__global__ void prep_x(const float* __restrict__ raw) {
    int idx = blockIdx.x * blockDim.x + threadIdx.x;
    if (idx >= NB * NS) return;
    int i = idx / NS, c = idx % NS;
    g_x[idx] = __float2half_rn(raw[(size_t)g_perm[i] * NS + c]);
}

// ---------------------------------------------------------------------------
// Transpose W[mat][K][N] -> WT[mat][N][K] (fp16).
// ---------------------------------------------------------------------------
__global__ void transpose_k(const float* __restrict__ src, int dsel, int K, int N,
                            long srcStride, long dstStride, long dstOff)
{
    __half* dst = (dsel == 1) ? g_wt1 : (dsel == 2) ? g_wt2 : (dsel == 3) ? g_wt3 : g_wt4;
    int mat = blockIdx.z;
    src += (size_t)mat * srcStride;
    dst += (size_t)mat * dstStride + dstOff;
    __shared__ float t[32][33];
    int x = blockIdx.x * 32 + threadIdx.x;  // N index
    int y0 = blockIdx.y * 32;               // K base
#pragma unroll
    for (int i = threadIdx.y; i < 32; i += 8)
        t[i][threadIdx.x] = src[(size_t)(y0 + i) * N + x];
    __syncthreads();
    int xo = blockIdx.x * 32;
#pragma unroll
    for (int i = threadIdx.y; i < 32; i += 8)
        dst[(size_t)(xo + i) * K + y0 + threadIdx.x] = __float2half_rn(t[threadIdx.x][i]);
}

// ---------------------------------------------------------------------------
// Grouped GEMM via mma.sync fp16 (f32 accumulate) + ldmatrix fragments.
// C[tile rows, n0:n0+128] = act(A @ WT^T + bias).
// 8 warps = 2(M) x 4(N); warp tile 64x32; per BK=32 chunk: 2 k16 steps.
// ---------------------------------------------------------------------------
template <int ACT, int OUT_PERM, int OUTF>
__global__ void __launch_bounds__(256, 2)
gemm_f16(int asel, int bsel, int csel,
         float* __restrict__ Cf,
         const float* __restrict__ bp, const float* __restrict__ bq,
         int K, int N, int wslot_g)
{
    int bx = blockIdx.x;
    if (bx >= g_ntiles) return;
    int g   = g_tile_g[bx];
    int m0  = g_tile_m0[bx];
    int end = g_goff[g + 1];
    int n0  = (int)blockIdx.y * BN;

    const __half* A = (asel == 0) ? g_x : (asel == 1) ? g_h1 : (asel == 2) ? g_mid : g_h2;
    __half* Ch = (csel == 1) ? g_h1 : (csel == 2) ? g_mid : g_h2;
    int slot = wslot_g ? g : (g >> 1);
    const __half* BT = ((bsel == 1) ? g_wt1 : (bsel == 2) ? g_wt2 : (bsel == 3) ? g_wt3 : g_wt4)
                       + (size_t)slot * (size_t)N * (size_t)K;
    const float* bias = ((g & 1) ? bq : bp) + (size_t)(g >> 1) * N + n0;

    const __half* Ag = A + (size_t)m0 * K;
    const __half* Bg = BT + (size_t)n0 * K;

    extern __shared__ __half smem[];
    uint32_t sa = smem_u32(smem);
    uint32_t sb = sa + STAGES * STAGE_BYTES;

    int tid = threadIdx.x, wid = tid >> 5, lid = tid & 31;
    int gi = lid >> 2, t = lid & 3;
    int mw = (wid & 1) * 64;
    int nw = (wid >> 1) * 32;

    // ldmatrix per-lane offsets (in halves)
    int aj = lid >> 3, ar = lid & 7;
    int a_off = (mw + (aj & 1) * 8 + ar) * HPITCH + (aj >> 1) * 8;
    int b_off = ((aj >> 1) * 8 + ar) * HPITCH + (aj & 1) * 8;   // + (nw + h*16)*HPITCH

    float acc[4][4][4];
#pragma unroll
    for (int i = 0; i < 4; i++)
#pragma unroll
        for (int j = 0; j < 4; j++)
#pragma unroll
            for (int k = 0; k < 4; k++) acc[i][j][k] = 0.0f;

    int nchunks = K / BK;

    auto load_chunk = [&](int c, int s) {
        int k0 = c * BK;
        uint32_t as = sa + s * STAGE_BYTES, bs = sb + s * STAGE_BYTES;
#pragma unroll
        for (int i = 0; i < 2; i++) {
            int f = tid + (i << 8);              // 0..511
            int row = f >> 2, c8 = (f & 3) << 3; // 8-half groups
            uint32_t so = (uint32_t)(row * HPITCH + c8) * 2;
            cp16(as + so, Ag + (size_t)row * K + k0 + c8);
            cp16(bs + so, Bg + (size_t)row * K + k0 + c8);
        }
        cp_commit();
    };

    int pl = nchunks < STAGES ? nchunks : STAGES;
    for (int c = 0; c < pl; c++) load_chunk(c, c);

    for (int c = 0; c < nchunks; c++) {
        int s = c % STAGES;
        if (c + STAGES <= nchunks) { cp_wait<STAGES - 1>(); } else { cp_wait<0>(); }
        __syncthreads();

        uint32_t as = sa + s * STAGE_BYTES, bs = sb + s * STAGE_BYTES;
#pragma unroll
        for (int ks = 0; ks < 2; ks++) {
            uint32_t bf[4][2];
#pragma unroll
            for (int h = 0; h < 2; h++) {
                uint32_t baddr = bs + (uint32_t)(b_off + (nw + h * 16) * HPITCH + ks * 16) * 2;
                ldsm4(bf[h * 2][0], bf[h * 2][1], bf[h * 2 + 1][0], bf[h * 2 + 1][1], baddr);
            }
#pragma unroll
            for (int mt = 0; mt < 4; mt++) {
                uint32_t a0, a1, a2, a3;
                uint32_t aaddr = as + (uint32_t)(a_off + mt * 16 * HPITCH + ks * 16) * 2;
                ldsm4(a0, a1, a2, a3, aaddr);
#pragma unroll
                for (int nt = 0; nt < 4; nt++)
                    mma_f16(acc[mt][nt], a0, a1, a2, a3, bf[nt][0], bf[nt][1]);
            }
        }
        __syncthreads();
        int cn = c + STAGES;
        if (cn < nchunks) load_chunk(cn, s);
    }

    // Epilogue: bias + activation + store (fp16 scratch or fp32 out)
#pragma unroll
    for (int mt = 0; mt < 4; mt++) {
        int r0 = m0 + mw + mt * 16 + gi;
        int r1 = r0 + 8;
        bool v0 = r0 < end, v1 = r1 < end;
        int o0 = v0 ? (OUT_PERM ? g_perm[r0] : r0) : 0;
        int o1 = v1 ? (OUT_PERM ? g_perm[r1] : r1) : 0;
#pragma unroll
        for (int nt = 0; nt < 4; nt++) {
            int lc = nw + nt * 8 + 2 * t;
            float b0v = bias[lc], b1v = bias[lc + 1];
            float x0 = acc[mt][nt][0] + b0v, x1 = acc[mt][nt][1] + b1v;
            float x2 = acc[mt][nt][2] + b0v, x3 = acc[mt][nt][3] + b1v;
            if (ACT) {
                x0 = gelu_exact(x0); x1 = gelu_exact(x1);
                x2 = gelu_exact(x2); x3 = gelu_exact(x3);
            }
            if (OUTF) {
                if (v0) *(float2*)(Cf + (size_t)o0 * N + n0 + lc) = make_float2(x0, x1);
                if (v1) *(float2*)(Cf + (size_t)o1 * N + n0 + lc) = make_float2(x2, x3);
            } else {
                if (v0) *(__half2*)(Ch + (size_t)o0 * N + n0 + lc) =
                    __halves2half2(__float2half_rn(x0), __float2half_rn(x1));
                if (v1) *(__half2*)(Ch + (size_t)o1 * N + n0 + lc) =
                    __halves2half2(__float2half_rn(x2), __float2half_rn(x3));
            }
        }
    }
}

// ---------------------------------------------------------------------------
// Row-wise LayerNorm over g_mid (fp16, permuted rows), in place.
// ---------------------------------------------------------------------------
__global__ void ln_kernel(const int* __restrict__ ei,
                          const float* __restrict__ ln_g,
                          const float* __restrict__ ln_b)
{
    int r = blockIdx.x;
    int orig = g_perm[r];
    int e = ei[orig];
    __half* row = g_mid + (size_t)r * ND;
    int t = threadIdx.x;

    float v[4];
    float s = 0.0f;
#pragma unroll
    for (int i = 0; i < 4; i++) { v[i] = __half2float(row[t + i * 256]); s += v[i]; }

    __shared__ float red[256];
    red[t] = s; __syncthreads();
    for (int o = 128; o > 0; o >>= 1) { if (t < o) red[t] += red[t + o]; __syncthreads(); }
    float mu = red[0] * (1.0f / ND);
    __syncthreads();

    float q = 0.0f;
#pragma unroll
    for (int i = 0; i < 4; i++) { float d = v[i] - mu; q += d * d; }
    red[t] = q; __syncthreads();
    for (int o = 128; o > 0; o >>= 1) { if (t < o) red[t] += red[t + o]; __syncthreads(); }
    float var = red[0] * (1.0f / ND);
    float inv = rsqrtf(var + 1e-5f);

#pragma unroll
    for (int i = 0; i < 4; i++) {
        int c = t + i * 256;
        row[c] = __float2half_rn((v[i] - mu) * inv * ln_g[(size_t)e * ND + c]
                                 + ln_b[(size_t)e * ND + c]);
    }
}

// ---------------------------------------------------------------------------
extern "C" void kernel_launch(void* const* d_in, const int* in_sizes, int n_in,
                              void* d_out, int out_size)
{
    const float* raw = (const float*)d_in[0];
    const int*   hp  = (const int*)d_in[1];
    const int*   ei  = (const int*)d_in[2];
    const float* pw1 = (const float*)d_in[3],  *pb1 = (const float*)d_in[4];
    const float* pw2 = (const float*)d_in[5],  *pb2 = (const float*)d_in[6];
    const float* qw1 = (const float*)d_in[7],  *qb1 = (const float*)d_in[8];
    const float* qw2 = (const float*)d_in[9],  *qb2 = (const float*)d_in[10];
    const float* lg  = (const float*)d_in[11], *lb  = (const float*)d_in[12];
    const float* tw1 = (const float*)d_in[13], *tb1 = (const float*)d_in[14];
    const float* tw2 = (const float*)d_in[15], *tb2 = (const float*)d_in[16];
    float* out = (float*)d_out;

    cudaFuncSetAttribute(gemm_f16<1, 0, 0>, cudaFuncAttributeMaxDynamicSharedMemorySize, SMEM_BYTES);
    cudaFuncSetAttribute(gemm_f16<0, 0, 0>, cudaFuncAttributeMaxDynamicSharedMemorySize, SMEM_BYTES);
    cudaFuncSetAttribute(gemm_f16<0, 1, 1>, cudaFuncAttributeMaxDynamicSharedMemorySize, SMEM_BYTES);

    sort_kernel<<<1, 256>>>(ei, hp);
    prep_x<<<(NB * NS + 255) / 256, 256>>>(raw);

    // Weight transposes (fp32 -> fp16): W[K][N] -> WT[N][K]
    dim3 tb(32, 8);
    transpose_k<<<dim3(NH / 32, NS / 32, NE), tb>>>(pw1, 1, NS, NH, (long)NS * NH, 2L * NH * NS, 0);
    transpose_k<<<dim3(NH / 32, NS / 32, NE), tb>>>(qw1, 1, NS, NH, (long)NS * NH, 2L * NH * NS, (long)NH * NS);
    transpose_k<<<dim3(ND / 32, NH / 32, NE), tb>>>(pw2, 2, NH, ND, (long)NH * ND, 2L * ND * NH, 0);
    transpose_k<<<dim3(ND / 32, NH / 32, NE), tb>>>(qw2, 2, NH, ND, (long)NH * ND, 2L * ND * NH, (long)ND * NH);
    transpose_k<<<dim3(NH / 32, ND / 32, NE), tb>>>(tw1, 3, ND, NH, (long)ND * NH, (long)NH * ND, 0);
    transpose_k<<<dim3(ND / 32, NH / 32, NE), tb>>>(tw2, 4, NH, ND, (long)NH * ND, (long)ND * NH, 0);

    // Stage 1: h1 = gelu(x @ w1 + b1)   [B,64] -> [B,2048]
    gemm_f16<1, 0, 0><<<dim3(MAXTILES, NH / BN), 256, SMEM_BYTES>>>(
        0, 1, 1, nullptr, pb1, qb1, NS, NH, 1);
    // Stage 2: mixed = h1 @ w2 + b2     [B,2048] -> [B,1024]
    gemm_f16<0, 0, 0><<<dim3(MAXTILES, ND / BN), 256, SMEM_BYTES>>>(
        1, 2, 2, nullptr, pb2, qb2, NH, ND, 1);
    // LayerNorm (in place on g_mid)
    ln_kernel<<<NB, 256>>>(ei, lg, lb);
    // Stage 3: h2 = gelu(normed @ tw1 + tb1)  [B,1024] -> [B,2048]
    gemm_f16<1, 0, 0><<<dim3(MAXTILES, NH / BN), 256, SMEM_BYTES>>>(
        2, 3, 3, nullptr, tb1, tb1, ND, NH, 0);
    // Stage 4: out = h2 @ tw2 + tb2, scatter to original rows
    gemm_f16<0, 1, 1><<<dim3(MAXTILES, ND / BN), 256, SMEM_BYTES>>>(
        3, 4, 0, out, tb2, tb2, NH, ND, 0);
}

// round 15
// speedup vs baseline: 4.5823x; 1.0743x over previous
#include <cuda_runtime.h>
#include <cuda_fp16.h>
#include <math.h>
#include <stdint.h>

#define NB 8192
#define NS 64
#define NH 2048
#define ND 1024
#define NE 8
#define NGROUP 16
#define BM 128
#define BN 128
#define BK 64
#define STAGES 3
#define HPITCH 72                          // halves; 144B = 9x16B (odd) -> conflict-free ldmatrix
#define STAGE_H (128 * HPITCH)
#define STAGE_BYTES (STAGE_H * 2)          // 18432 B
#define SMEM_BYTES (STAGES * 2 * STAGE_BYTES)   // 110592 B -> 2 CTAs/SM
#define MAXTILES 80

// ---------------- device scratch (allowed: __device__ globals) --------------
__device__ __align__(128) __half g_x  [(NB + BM) * NS];
__device__ __align__(128) __half g_h1 [(NB + BM) * NH];
__device__ __align__(128) __half g_mid[(NB + BM) * ND];
__device__ __align__(128) __half g_h2 [(NB + BM) * NH];
__device__ __align__(128) __half g_wt1[NGROUP * NH * NS];   // [16][2048][64]  ([N][K])
__device__ __align__(128) __half g_wt2[NGROUP * ND * NH];
__device__ __align__(128) __half g_wt3[NE * NH * ND];
__device__ __align__(128) __half g_wt4[NE * ND * NH];
__device__ int g_perm[NB];
__device__ int g_goff[NGROUP + 1];
__device__ int g_pos[NGROUP];
__device__ int g_tile_g[MAXTILES];
__device__ int g_tile_m0[MAXTILES];
__device__ int g_ntiles;

// ---------------- helpers ---------------------------------------------------
__device__ __forceinline__ uint32_t smem_u32(const void* p) {
    uint32_t a;
    asm("{ .reg .u64 t; cvta.to.shared.u64 t, %1; cvt.u32.u64 %0, t; }" : "=r"(a) : "l"(p));
    return a;
}
__device__ __forceinline__ void cp16(uint32_t d, const void* s) {
    asm volatile("cp.async.cg.shared.global [%0], [%1], 16;" :: "r"(d), "l"(s));
}
__device__ __forceinline__ void cp_commit() { asm volatile("cp.async.commit_group;" ::: "memory"); }
template <int N_> __device__ __forceinline__ void cp_wait() {
    asm volatile("cp.async.wait_group %0;" :: "n"(N_) : "memory");
}
__device__ __forceinline__ void ldsm4(uint32_t& r0, uint32_t& r1, uint32_t& r2, uint32_t& r3,
                                      uint32_t addr) {
    asm volatile("ldmatrix.sync.aligned.m8n8.x4.shared.b16 {%0,%1,%2,%3}, [%4];"
                 : "=r"(r0), "=r"(r1), "=r"(r2), "=r"(r3) : "r"(addr));
}
__device__ __forceinline__ void mma_f16(float* d, uint32_t a0, uint32_t a1, uint32_t a2,
                                        uint32_t a3, uint32_t b0, uint32_t b1) {
    asm volatile(
        "mma.sync.aligned.m16n8k16.row.col.f32.f16.f16.f32 "
        "{%0,%1,%2,%3}, {%4,%5,%6,%7}, {%8,%9}, {%0,%1,%2,%3};"
        : "+f"(d[0]), "+f"(d[1]), "+f"(d[2]), "+f"(d[3])
        : "r"(a0), "r"(a1), "r"(a2), "r"(a3), "r"(b0), "r"(b1));
}
__device__ __forceinline__ float gelu_exact(float x) {
    return 0.5f * x * (1.0f + erff(x * 0.70710678118654752f));
}

// ---------------------------------------------------------------------------
// Sort rows by (expert, sel); build group offsets + tile list.
// ---------------------------------------------------------------------------
__global__ void sort_kernel(const int* __restrict__ ei, const int* __restrict__ hp) {
    __shared__ int cnt[NGROUP];
    int t = threadIdx.x;
    if (t < NGROUP) cnt[t] = 0;
    __syncthreads();
    for (int i = t; i < NB; i += blockDim.x)
        atomicAdd(&cnt[ei[i] * 2 + (hp[i] != 0)], 1);
    __syncthreads();
    if (t == 0) {
        int acc = 0;
        for (int k = 0; k < NGROUP; k++) { g_goff[k] = acc; g_pos[k] = acc; acc += cnt[k]; }
        g_goff[NGROUP] = acc;
        int nt = 0;
        for (int g = 0; g < NGROUP; g++)
            for (int m0 = g_goff[g]; m0 < g_goff[g + 1]; m0 += BM) {
                g_tile_g[nt] = g; g_tile_m0[nt] = m0; nt++;
            }
        g_ntiles = nt;   // <= 16 + 64 = 80
    }
    __syncthreads();
    for (int i = t; i < NB; i += blockDim.x) {
        int key = ei[i] * 2 + (hp[i] != 0);
        g_perm[atomicAdd(&g_pos[key], 1)] = i;
    }
}

// ---------------------------------------------------------------------------
// g_x[i][:] = fp16(raw[g_perm[i]][:])
// ---------------------------------------------------------------------------
__global__ void prep_x(const float* __restrict__ raw) {
    int idx = blockIdx.x * blockDim.x + threadIdx.x;
    if (idx >= NB * NS) return;
    int i = idx / NS, c = idx % NS;
    g_x[idx] = __float2half_rn(raw[(size_t)g_perm[i] * NS + c]);
}

// ---------------------------------------------------------------------------
// Transpose W[mat][K][N] -> WT[mat][N][K] (fp16). grid.z = mats; when two
// source tensors (p/q interleave), mat z: e = z>>1, sel = z&1.
// ---------------------------------------------------------------------------
__global__ void transpose_k(const float* __restrict__ srcP, const float* __restrict__ srcQ,
                            int dsel, int K, int N, int interleave)
{
    __half* dst = (dsel == 1) ? g_wt1 : (dsel == 2) ? g_wt2 : (dsel == 3) ? g_wt3 : g_wt4;
    int z = blockIdx.z;
    const float* src;
    if (interleave) {
        int e = z >> 1, sel = z & 1;
        src = (sel ? srcQ : srcP) + (size_t)e * K * N;
    } else {
        src = srcP + (size_t)z * K * N;
    }
    dst += (size_t)z * (size_t)N * K;
    __shared__ float t[32][33];
    int x = blockIdx.x * 32 + threadIdx.x;  // N index
    int y0 = blockIdx.y * 32;               // K base
#pragma unroll
    for (int i = threadIdx.y; i < 32; i += 8)
        t[i][threadIdx.x] = src[(size_t)(y0 + i) * N + x];
    __syncthreads();
    int xo = blockIdx.x * 32;
#pragma unroll
    for (int i = threadIdx.y; i < 32; i += 8)
        dst[(size_t)(xo + i) * K + y0 + threadIdx.x] = __float2half_rn(t[threadIdx.x][i]);
}

// ---------------------------------------------------------------------------
// Grouped GEMM via mma.sync fp16 + ldmatrix. Single __syncthreads per chunk,
// loads issued before MMA (CUTLASS multistage order). BK=64, 3 stages.
// 8 warps = 2(M) x 4(N); warp tile 64x32.
// ---------------------------------------------------------------------------
template <int ACT, int OUT_PERM, int OUTF>
__global__ void __launch_bounds__(256, 2)
gemm_f16(int asel, int bsel, int csel,
         float* __restrict__ Cf,
         const float* __restrict__ bp, const float* __restrict__ bq,
         int K, int N, int wslot_g)
{
    int bx = blockIdx.x;
    if (bx >= g_ntiles) return;
    int g   = g_tile_g[bx];
    int m0  = g_tile_m0[bx];
    int end = g_goff[g + 1];
    int n0  = (int)blockIdx.y * BN;

    const __half* A = (asel == 0) ? g_x : (asel == 1) ? g_h1 : (asel == 2) ? g_mid : g_h2;
    __half* Ch = (csel == 1) ? g_h1 : (csel == 2) ? g_mid : g_h2;
    int slot = wslot_g ? g : (g >> 1);
    const __half* BT = ((bsel == 1) ? g_wt1 : (bsel == 2) ? g_wt2 : (bsel == 3) ? g_wt3 : g_wt4)
                       + (size_t)slot * (size_t)N * (size_t)K;
    const float* bias = ((g & 1) ? bq : bp) + (size_t)(g >> 1) * N + n0;

    const __half* Ag = A + (size_t)m0 * K;
    const __half* Bg = BT + (size_t)n0 * K;

    extern __shared__ __half smem[];
    uint32_t sa = smem_u32(smem);
    uint32_t sb = sa + STAGES * STAGE_BYTES;

    int tid = threadIdx.x, wid = tid >> 5, lid = tid & 31;
    int gi = lid >> 2, t = lid & 3;
    int mw = (wid & 1) * 64;
    int nw = (wid >> 1) * 32;

    // ldmatrix per-lane offsets (in halves)
    int aj = lid >> 3, ar = lid & 7;
    int a_off = (mw + (aj & 1) * 8 + ar) * HPITCH + (aj >> 1) * 8;
    int b_off = ((aj >> 1) * 8 + ar) * HPITCH + (aj & 1) * 8;   // + (nw + h*16)*HPITCH

    float acc[4][4][4];
#pragma unroll
    for (int i = 0; i < 4; i++)
#pragma unroll
        for (int j = 0; j < 4; j++)
#pragma unroll
            for (int k = 0; k < 4; k++) acc[i][j][k] = 0.0f;

    int nchunks = K / BK;

    auto load_chunk = [&](int c, int s) {
        int k0 = c * BK;
        uint32_t as = sa + s * STAGE_BYTES, bs = sb + s * STAGE_BYTES;
#pragma unroll
        for (int i = 0; i < 4; i++) {
            int f = tid + (i << 8);              // 0..1023
            int row = f >> 3, c8 = (f & 7) << 3; // 8 halves (16B) per cp
            uint32_t so = (uint32_t)(row * HPITCH + c8) * 2;
            cp16(as + so, Ag + (size_t)row * K + k0 + c8);
            cp16(bs + so, Bg + (size_t)row * K + k0 + c8);
        }
        cp_commit();
    };

    int pl = nchunks < (STAGES - 1) ? nchunks : (STAGES - 1);
    for (int c = 0; c < pl; c++) load_chunk(c, c);

    for (int c = 0; c < nchunks; c++) {
        int s = c % STAGES;
        if (c + 2 <= nchunks) { cp_wait<1>(); } else { cp_wait<0>(); }
        __syncthreads();
        int cn = c + STAGES - 1;
        if (cn < nchunks) load_chunk(cn, cn % STAGES);   // overwrites stage consumed at c-1

        uint32_t as = sa + s * STAGE_BYTES, bs = sb + s * STAGE_BYTES;
#pragma unroll
        for (int ks = 0; ks < 4; ks++) {
            uint32_t bf[4][2];
#pragma unroll
            for (int h = 0; h < 2; h++) {
                uint32_t baddr = bs + (uint32_t)(b_off + (nw + h * 16) * HPITCH + ks * 16) * 2;
                ldsm4(bf[h * 2][0], bf[h * 2][1], bf[h * 2 + 1][0], bf[h * 2 + 1][1], baddr);
            }
#pragma unroll
            for (int mt = 0; mt < 4; mt++) {
                uint32_t a0, a1, a2, a3;
                uint32_t aaddr = as + (uint32_t)(a_off + mt * 16 * HPITCH + ks * 16) * 2;
                ldsm4(a0, a1, a2, a3, aaddr);
#pragma unroll
                for (int nt = 0; nt < 4; nt++)
                    mma_f16(acc[mt][nt], a0, a1, a2, a3, bf[nt][0], bf[nt][1]);
            }
        }
    }

    // Epilogue: bias + activation + store (fp16 scratch or fp32 out)
#pragma unroll
    for (int mt = 0; mt < 4; mt++) {
        int r0 = m0 + mw + mt * 16 + gi;
        int r1 = r0 + 8;
        bool v0 = r0 < end, v1 = r1 < end;
        int o0 = v0 ? (OUT_PERM ? g_perm[r0] : r0) : 0;
        int o1 = v1 ? (OUT_PERM ? g_perm[r1] : r1) : 0;
#pragma unroll
        for (int nt = 0; nt < 4; nt++) {
            int lc = nw + nt * 8 + 2 * t;
            float b0v = bias[lc], b1v = bias[lc + 1];
            float x0 = acc[mt][nt][0] + b0v, x1 = acc[mt][nt][1] + b1v;
            float x2 = acc[mt][nt][2] + b0v, x3 = acc[mt][nt][3] + b1v;
            if (ACT) {
                x0 = gelu_exact(x0); x1 = gelu_exact(x1);
                x2 = gelu_exact(x2); x3 = gelu_exact(x3);
            }
            if (OUTF) {
                if (v0) *(float2*)(Cf + (size_t)o0 * N + n0 + lc) = make_float2(x0, x1);
                if (v1) *(float2*)(Cf + (size_t)o1 * N + n0 + lc) = make_float2(x2, x3);
            } else {
                if (v0) *(__half2*)(Ch + (size_t)o0 * N + n0 + lc) =
                    __halves2half2(__float2half_rn(x0), __float2half_rn(x1));
                if (v1) *(__half2*)(Ch + (size_t)o1 * N + n0 + lc) =
                    __halves2half2(__float2half_rn(x2), __float2half_rn(x3));
            }
        }
    }
}

// ---------------------------------------------------------------------------
// Row-wise LayerNorm over g_mid (fp16, permuted rows), in place.
// ---------------------------------------------------------------------------
__global__ void ln_kernel(const int* __restrict__ ei,
                          const float* __restrict__ ln_g,
                          const float* __restrict__ ln_b)
{
    int r = blockIdx.x;
    int orig = g_perm[r];
    int e = ei[orig];
    __half* row = g_mid + (size_t)r * ND;
    int t = threadIdx.x;

    float v[4];
    float s = 0.0f;
#pragma unroll
    for (int i = 0; i < 4; i++) { v[i] = __half2float(row[t + i * 256]); s += v[i]; }

    __shared__ float red[256];
    red[t] = s; __syncthreads();
    for (int o = 128; o > 0; o >>= 1) { if (t < o) red[t] += red[t + o]; __syncthreads(); }
    float mu = red[0] * (1.0f / ND);
    __syncthreads();

    float q = 0.0f;
#pragma unroll
    for (int i = 0; i < 4; i++) { float d = v[i] - mu; q += d * d; }
    red[t] = q; __syncthreads();
    for (int o = 128; o > 0; o >>= 1) { if (t < o) red[t] += red[t + o]; __syncthreads(); }
    float var = red[0] * (1.0f / ND);
    float inv = rsqrtf(var + 1e-5f);

#pragma unroll
    for (int i = 0; i < 4; i++) {
        int c = t + i * 256;
        row[c] = __float2half_rn((v[i] - mu) * inv * ln_g[(size_t)e * ND + c]
                                 + ln_b[(size_t)e * ND + c]);
    }
}

// ---------------------------------------------------------------------------
extern "C" void kernel_launch(void* const* d_in, const int* in_sizes, int n_in,
                              void* d_out, int out_size)
{
    const float* raw = (const float*)d_in[0];
    const int*   hp  = (const int*)d_in[1];
    const int*   ei  = (const int*)d_in[2];
    const float* pw1 = (const float*)d_in[3],  *pb1 = (const float*)d_in[4];
    const float* pw2 = (const float*)d_in[5],  *pb2 = (const float*)d_in[6];
    const float* qw1 = (const float*)d_in[7],  *qb1 = (const float*)d_in[8];
    const float* qw2 = (const float*)d_in[9],  *qb2 = (const float*)d_in[10];
    const float* lg  = (const float*)d_in[11], *lb  = (const float*)d_in[12];
    const float* tw1 = (const float*)d_in[13], *tb1 = (const float*)d_in[14];
    const float* tw2 = (const float*)d_in[15], *tb2 = (const float*)d_in[16];
    float* out = (float*)d_out;

    cudaFuncSetAttribute(gemm_f16<1, 0, 0>, cudaFuncAttributeMaxDynamicSharedMemorySize, SMEM_BYTES);
    cudaFuncSetAttribute(gemm_f16<0, 0, 0>, cudaFuncAttributeMaxDynamicSharedMemorySize, SMEM_BYTES);
    cudaFuncSetAttribute(gemm_f16<0, 1, 1>, cudaFuncAttributeMaxDynamicSharedMemorySize, SMEM_BYTES);

    sort_kernel<<<1, 256>>>(ei, hp);
    prep_x<<<(NB * NS + 255) / 256, 256>>>(raw);

    // Weight transposes (fp32 -> fp16): W[K][N] -> WT[N][K]
    dim3 tb(32, 8);
    transpose_k<<<dim3(NH / 32, NS / 32, NGROUP), tb>>>(pw1, qw1, 1, NS, NH, 1);
    transpose_k<<<dim3(ND / 32, NH / 32, NGROUP), tb>>>(pw2, qw2, 2, NH, ND, 1);
    transpose_k<<<dim3(NH / 32, ND / 32, NE),     tb>>>(tw1, nullptr, 3, ND, NH, 0);
    transpose_k<<<dim3(ND / 32, NH / 32, NE),     tb>>>(tw2, nullptr, 4, NH, ND, 0);

    // Stage 1: h1 = gelu(x @ w1 + b1)   [B,64] -> [B,2048]
    gemm_f16<1, 0, 0><<<dim3(MAXTILES, NH / BN), 256, SMEM_BYTES>>>(
        0, 1, 1, nullptr, pb1, qb1, NS, NH, 1);
    // Stage 2: mixed = h1 @ w2 + b2     [B,2048] -> [B,1024]
    gemm_f16<0, 0, 0><<<dim3(MAXTILES, ND / BN), 256, SMEM_BYTES>>>(
        1, 2, 2, nullptr, pb2, qb2, NH, ND, 1);
    // LayerNorm (in place on g_mid)
    ln_kernel<<<NB, 256>>>(ei, lg, lb);
    // Stage 3: h2 = gelu(normed @ tw1 + tb1)  [B,1024] -> [B,2048]
    gemm_f16<1, 0, 0><<<dim3(MAXTILES, NH / BN), 256, SMEM_BYTES>>>(
        2, 3, 3, nullptr, tb1, tb1, ND, NH, 0);
    // Stage 4: out = h2 @ tw2 + tb2, scatter to original rows
    gemm_f16<0, 1, 1><<<dim3(MAXTILES, ND / BN), 256, SMEM_BYTES>>>(
        3, 4, 0, out, tb2, tb2, NH, ND, 0);
}